// round 8
// baseline (speedup 1.0000x reference)
#include <cuda_runtime.h>
#include <cuda_bf16.h>
#include <cstdint>

// Off-diagonal Gram sum via:
//   (1/D) sum_d [ (sum_b x2[b,d])^2 - sum_b x2[b,d]^2 ],  x2 = x*x.
//
// R8: push the only axis that moved the bench (warps/SM at fixed grid=147).
// 1024 threads/CTA (32 warps/SM), b-split 4-way: thread (c, q) stages
// 8 unpredicated LDG.128 for rows q*8..q*8+7 of column c. Column sums s
// recombined via a 16KB smem exchange across the 4 quarters; the x^4
// term is additive. Packed f32x2 math in the inner loop.

#define B_ROWS 32
#define THREADS 1024
#define QROWS 8            // b-rows per thread (32 / 4 quarters)

__device__ double g_acc = 0.0;
__device__ unsigned int g_count = 0;

__device__ __forceinline__ unsigned long long pk2(float lo, float hi) {
    unsigned long long r;
    asm("mov.b64 %0, {%1, %2};" : "=l"(r) : "f"(lo), "f"(hi));
    return r;
}
__device__ __forceinline__ void upk2(unsigned long long v, float& lo, float& hi) {
    asm("mov.b64 {%0, %1}, %2;" : "=f"(lo), "=f"(hi) : "l"(v));
}
__device__ __forceinline__ unsigned long long mul2(unsigned long long a, unsigned long long b) {
    unsigned long long r;
    asm("mul.rn.f32x2 %0, %1, %2;" : "=l"(r) : "l"(a), "l"(b));
    return r;
}
__device__ __forceinline__ unsigned long long add2(unsigned long long a, unsigned long long b) {
    unsigned long long r;
    asm("add.rn.f32x2 %0, %1, %2;" : "=l"(r) : "l"(a), "l"(b));
    return r;
}
__device__ __forceinline__ unsigned long long fma2(unsigned long long a, unsigned long long b,
                                                   unsigned long long c) {
    unsigned long long r;
    asm("fma.rn.f32x2 %0, %1, %2, %3;" : "=l"(r) : "l"(a), "l"(b), "l"(c));
    return r;
}

__global__ void __launch_bounds__(THREADS, 1)
ortho_fused_kernel(const float4* __restrict__ in,
                   float* __restrict__ out,
                   int d4, double inv_d) {
    const int tid = threadIdx.x;
    const int c   = tid & 255;              // column slot within CTA
    const int q   = tid >> 8;               // b-quarter: 0..3
    const int col = blockIdx.x * 256 + c;   // grid covers d4 exactly

    // 8 unpredicated staged loads: rows q*8 .. q*8+7 of column `col`
    const float4* p = in + (size_t)(q * QROWS) * d4 + col;
    float4 v[QROWS];
    #pragma unroll
    for (int j = 0; j < QROWS; j++)
        v[j] = p[(size_t)j * d4];

    unsigned long long s01 = 0ull, s23 = 0ull, t01 = 0ull, t23 = 0ull;
    #pragma unroll
    for (int j = 0; j < QROWS; j++) {
        unsigned long long v01 = pk2(v[j].x, v[j].y);
        unsigned long long v23 = pk2(v[j].z, v[j].w);
        unsigned long long a01 = mul2(v01, v01);
        unsigned long long a23 = mul2(v23, v23);
        s01 = add2(s01, a01);
        s23 = add2(s23, a23);
        t01 = fma2(a01, a01, t01);
        t23 = fma2(a23, a23, t23);
    }

    float sx, sy, sz, sw, tx, ty, tz, tw;
    upk2(s01, sx, sy); upk2(s23, sz, sw);
    upk2(t01, tx, ty); upk2(t23, tz, tw);
    float tsum = (tx + ty) + (tz + tw);

    // exchange partial s across the 4 b-quarters of each column
    __shared__ float4 spart[THREADS];
    spart[tid] = make_float4(sx, sy, sz, sw);
    __syncthreads();

    float val = -tsum;
    if (q == 0) {
        float4 o1 = spart[tid + 256];
        float4 o2 = spart[tid + 512];
        float4 o3 = spart[tid + 768];
        float fx = sx + o1.x + o2.x + o3.x;
        float fy = sy + o1.y + o2.y + o3.y;
        float fz = sz + o1.z + o2.z + o3.z;
        float fw = sw + o1.w + o2.w + o3.w;
        val += (fx * fx + fy * fy) + (fz * fz + fw * fw);
    }

    // float warp reduction
    #pragma unroll
    for (int off = 16; off > 0; off >>= 1)
        val += __shfl_xor_sync(0xFFFFFFFFu, val, off);

    __shared__ float warp_sums[THREADS / 32];
    int lane = tid & 31;
    int wid  = tid >> 5;
    if (lane == 0) warp_sums[wid] = val;
    __syncthreads();

    if (tid == 0) {
        double blk = 0.0;
        #pragma unroll
        for (int w = 0; w < THREADS / 32; w++) blk += (double)warp_sums[w];
        atomicAdd(&g_acc, blk);
        __threadfence();
        unsigned int ticket = atomicAdd(&g_count, 1u);
        if (ticket == gridDim.x - 1) {
            out[0] = (float)(g_acc * inv_d);
            g_acc = 0.0;     // reset for next graph replay
            g_count = 0u;
        }
    }
}

extern "C" void kernel_launch(void* const* d_in, const int* in_sizes, int n_in,
                              void* d_out, int out_size) {
    const float4* in = (const float4*)d_in[0];
    float* out = (float*)d_out;

    int total = in_sizes[0];           // 32 * 150528
    int D = total / B_ROWS;            // 150528
    int d4 = D / 4;                    // 37632 = 147 * 256

    int blocks = d4 / 256;             // 147, exact; 1024 threads per CTA
    ortho_fused_kernel<<<blocks, THREADS>>>(in, out, d4, 1.0 / (double)D);
}

// round 9
// speedup vs baseline: 1.2610x; 1.2610x over previous
#include <cuda_runtime.h>
#include <cuda_bf16.h>
#include <cstdint>

// Off-diagonal Gram sum via:
//   (1/D) sum_d [ (sum_b x2[b,d])^2 - sum_b x2[b,d]^2 ],  x2 = x*x.
//
// R9: 32 warps/SM WITHOUT the 1024-thread register ceiling that broke R8.
// grid=294 (2 CTAs/SM) x 512 threads. b-split 4-way inside each warp
// (lane = 8q + c): thread stages 8 unpredicated LDG.128 for rows
// q*8..q*8+7 of column w*8+c. Each warp-load covers 4 fully-used 128B
// lines. s recombined with shfl_xor (no smem exchange); x^4 additive.

#define B_ROWS 32
#define THREADS 512
#define QROWS 8

__device__ double g_acc = 0.0;
__device__ unsigned int g_count = 0;

__device__ __forceinline__ unsigned long long pk2(float lo, float hi) {
    unsigned long long r;
    asm("mov.b64 %0, {%1, %2};" : "=l"(r) : "f"(lo), "f"(hi));
    return r;
}
__device__ __forceinline__ void upk2(unsigned long long v, float& lo, float& hi) {
    asm("mov.b64 {%0, %1}, %2;" : "=f"(lo), "=f"(hi) : "l"(v));
}
__device__ __forceinline__ unsigned long long mul2(unsigned long long a, unsigned long long b) {
    unsigned long long r;
    asm("mul.rn.f32x2 %0, %1, %2;" : "=l"(r) : "l"(a), "l"(b));
    return r;
}
__device__ __forceinline__ unsigned long long add2(unsigned long long a, unsigned long long b) {
    unsigned long long r;
    asm("add.rn.f32x2 %0, %1, %2;" : "=l"(r) : "l"(a), "l"(b));
    return r;
}
__device__ __forceinline__ unsigned long long fma2(unsigned long long a, unsigned long long b,
                                                   unsigned long long c) {
    unsigned long long r;
    asm("fma.rn.f32x2 %0, %1, %2, %3;" : "=l"(r) : "l"(a), "l"(b), "l"(c));
    return r;
}

__global__ void __launch_bounds__(THREADS, 2)
ortho_fused_kernel(const float4* __restrict__ in,
                   float* __restrict__ out,
                   int d4, double inv_d) {
    const int tid  = threadIdx.x;
    const int lane = tid & 31;
    const int q    = lane >> 3;                       // b-quarter 0..3
    const int c    = lane & 7;                        // column within warp
    const int gw   = blockIdx.x * (THREADS / 32) + (tid >> 5);  // global warp
    const int col  = gw * 8 + c;                      // exact: 4704*8 = 37632

    // 8 unpredicated staged loads: rows q*8 .. q*8+7 of column `col`
    const float4* p = in + (size_t)(q * QROWS) * d4 + col;
    float4 v[QROWS];
    #pragma unroll
    for (int j = 0; j < QROWS; j++)
        v[j] = p[(size_t)j * d4];

    unsigned long long s01 = 0ull, s23 = 0ull, t01 = 0ull, t23 = 0ull;
    #pragma unroll
    for (int j = 0; j < QROWS; j++) {
        unsigned long long v01 = pk2(v[j].x, v[j].y);
        unsigned long long v23 = pk2(v[j].z, v[j].w);
        unsigned long long a01 = mul2(v01, v01);
        unsigned long long a23 = mul2(v23, v23);
        s01 = add2(s01, a01);
        s23 = add2(s23, a23);
        t01 = fma2(a01, a01, t01);
        t23 = fma2(a23, a23, t23);
    }

    float sx, sy, sz, sw, tx, ty, tz, tw;
    upk2(s01, sx, sy); upk2(s23, sz, sw);
    upk2(t01, tx, ty); upk2(t23, tz, tw);
    float tsum = (tx + ty) + (tz + tw);

    // recombine s across the 4 b-quarters (lanes c, c+8, c+16, c+24)
    sx += __shfl_xor_sync(0xFFFFFFFFu, sx, 8);
    sx += __shfl_xor_sync(0xFFFFFFFFu, sx, 16);
    sy += __shfl_xor_sync(0xFFFFFFFFu, sy, 8);
    sy += __shfl_xor_sync(0xFFFFFFFFu, sy, 16);
    sz += __shfl_xor_sync(0xFFFFFFFFu, sz, 8);
    sz += __shfl_xor_sync(0xFFFFFFFFu, sz, 16);
    sw += __shfl_xor_sync(0xFFFFFFFFu, sw, 8);
    sw += __shfl_xor_sync(0xFFFFFFFFu, sw, 16);

    float val = -tsum;
    if (q == 0)
        val += (sx * sx + sy * sy) + (sz * sz + sw * sw);

    // float warp reduction
    #pragma unroll
    for (int off = 16; off > 0; off >>= 1)
        val += __shfl_xor_sync(0xFFFFFFFFu, val, off);

    __shared__ float warp_sums[THREADS / 32];
    int wid = tid >> 5;
    if (lane == 0) warp_sums[wid] = val;
    __syncthreads();

    if (tid == 0) {
        double blk = 0.0;
        #pragma unroll
        for (int w = 0; w < THREADS / 32; w++) blk += (double)warp_sums[w];
        atomicAdd(&g_acc, blk);
        __threadfence();
        unsigned int ticket = atomicAdd(&g_count, 1u);
        if (ticket == gridDim.x - 1) {
            out[0] = (float)(g_acc * inv_d);
            g_acc = 0.0;     // reset for next graph replay
            g_count = 0u;
        }
    }
}

extern "C" void kernel_launch(void* const* d_in, const int* in_sizes, int n_in,
                              void* d_out, int out_size) {
    const float4* in = (const float4*)d_in[0];
    float* out = (float*)d_out;

    int total = in_sizes[0];           // 32 * 150528
    int D = total / B_ROWS;            // 150528
    int d4 = D / 4;                    // 37632 = 294 * 16 * 8

    int blocks = d4 / ((THREADS / 32) * 8);   // 294, exact
    ortho_fused_kernel<<<blocks, THREADS>>>(in, out, d4, 1.0 / (double)D);
}